// round 1
// baseline (speedup 1.0000x reference)
#include <cuda_runtime.h>
#include <cuda_bf16.h>
#include <cstdint>

#define N_NODES 50000
#define N_EDGES 1600000
#define D 512

// ---------------- scratch (static device globals; no runtime alloc) ----------------
__device__ float g_support[(size_t)N_NODES * D];   // X @ W   (102.4 MB)
__device__ int   g_counts[N_NODES];
__device__ int   g_rowptr[N_NODES + 1];
__device__ int   g_cursor[N_NODES];
__device__ int   g_blksum[64];
__device__ int   g_cols[N_EDGES];
__device__ float g_wts[N_EDGES];

// ---------------- GEMM: support = X(50000x512) @ W(512x512) ----------------
#define BM 128
#define BN 128
#define BK 8
#define TM 8
#define TN 8

__global__ __launch_bounds__(256) void sgemm_kernel(const float* __restrict__ A,
                                                    const float* __restrict__ B,
                                                    int M) {
    const int K = D, N = D;
    __shared__ float As[BK][BM];
    __shared__ float Bs[BK][BN];

    int tid = threadIdx.x;
    int blockRow = blockIdx.y * BM;
    int blockCol = blockIdx.x * BN;

    int aRow = tid >> 1;            // 0..127
    int aCol = (tid & 1) * 4;       // 0 or 4
    int bRow = tid >> 5;            // 0..7
    int bCol = (tid & 31) * 4;      // 0..124

    int threadRow = (tid >> 4) * TM;  // 0..120
    int threadCol = (tid & 15) * TN;  // 0..120

    float acc[TM][TN];
#pragma unroll
    for (int i = 0; i < TM; i++)
#pragma unroll
        for (int j = 0; j < TN; j++) acc[i][j] = 0.f;

    float regM[TM], regN[TN];

    for (int k0 = 0; k0 < K; k0 += BK) {
        // A tile (with M guard), stored transposed As[k][m]
        {
            int gr = blockRow + aRow;
            float4 av = make_float4(0.f, 0.f, 0.f, 0.f);
            if (gr < M)
                av = *(const float4*)(A + (size_t)gr * K + k0 + aCol);
            As[aCol + 0][aRow] = av.x;
            As[aCol + 1][aRow] = av.y;
            As[aCol + 2][aRow] = av.z;
            As[aCol + 3][aRow] = av.w;
        }
        // B tile
        {
            float4 bv = *(const float4*)(B + (size_t)(k0 + bRow) * N + blockCol + bCol);
            *(float4*)&Bs[bRow][bCol] = bv;
        }
        __syncthreads();
#pragma unroll
        for (int k = 0; k < BK; k++) {
#pragma unroll
            for (int i = 0; i < TM; i++) regM[i] = As[k][threadRow + i];
#pragma unroll
            for (int j = 0; j < TN; j++) regN[j] = Bs[k][threadCol + j];
#pragma unroll
            for (int i = 0; i < TM; i++)
#pragma unroll
                for (int j = 0; j < TN; j++) acc[i][j] += regM[i] * regN[j];
        }
        __syncthreads();
    }

#pragma unroll
    for (int i = 0; i < TM; i++) {
        int gr = blockRow + threadRow + i;
        if (gr < M) {
            float* cp = g_support + (size_t)gr * N + blockCol + threadCol;
#pragma unroll
            for (int j = 0; j < TN; j += 4) {
                float4 v = make_float4(acc[i][j], acc[i][j + 1], acc[i][j + 2], acc[i][j + 3]);
                *(float4*)(cp + j) = v;
            }
        }
    }
}

// ---------------- CSR build ----------------
__global__ void zero_counts_kernel() {
    int i = blockIdx.x * blockDim.x + threadIdx.x;
    if (i < N_NODES) g_counts[i] = 0;
}

__global__ void hist_kernel(const int* __restrict__ row) {
    int e = blockIdx.x * blockDim.x + threadIdx.x;
    if (e < N_EDGES) atomicAdd(&g_counts[row[e]], 1);
}

#define SCAN_B 1024
#define SCAN_NBLK ((N_NODES + SCAN_B - 1) / SCAN_B)   // 49

__global__ __launch_bounds__(SCAN_B) void scan1_kernel() {
    __shared__ int sh[SCAN_B];
    int i = blockIdx.x * SCAN_B + threadIdx.x;
    int v = (i < N_NODES) ? g_counts[i] : 0;
    sh[threadIdx.x] = v;
    __syncthreads();
    // Hillis-Steele inclusive scan
    for (int off = 1; off < SCAN_B; off <<= 1) {
        int t = (threadIdx.x >= off) ? sh[threadIdx.x - off] : 0;
        __syncthreads();
        sh[threadIdx.x] += t;
        __syncthreads();
    }
    if (i < N_NODES) g_rowptr[i] = sh[threadIdx.x] - v;  // exclusive (within block)
    if (threadIdx.x == SCAN_B - 1) g_blksum[blockIdx.x] = sh[SCAN_B - 1];
}

__global__ void scan2_kernel() {
    if (threadIdx.x == 0) {
        int acc = 0;
        for (int b = 0; b < SCAN_NBLK; b++) {
            int t = g_blksum[b];
            g_blksum[b] = acc;
            acc += t;
        }
    }
}

__global__ __launch_bounds__(SCAN_B) void scan3_kernel() {
    int i = blockIdx.x * SCAN_B + threadIdx.x;
    if (i < N_NODES) {
        int v = g_rowptr[i] + g_blksum[blockIdx.x];
        g_rowptr[i] = v;
        g_cursor[i] = v;
    }
    if (i == 0) g_rowptr[N_NODES] = N_EDGES;
}

__global__ void scatter_kernel(const int* __restrict__ row, const int* __restrict__ col,
                               const float* __restrict__ ew) {
    int e = blockIdx.x * blockDim.x + threadIdx.x;
    if (e < N_EDGES) {
        int r = row[e];
        int p = atomicAdd(&g_cursor[r], 1);
        g_cols[p] = col[e];
        g_wts[p] = ew[e];
    }
}

// ---------------- SpMM: out[r] = sum_e w_e * support[col_e] + bias ----------------
__global__ __launch_bounds__(128) void spmm_kernel(const float* __restrict__ bias,
                                                   float* __restrict__ out) {
    int r = blockIdx.x;
    int start = g_rowptr[r];
    int end = g_rowptr[r + 1];
    int t = threadIdx.x;   // 128 threads x float4 = 512 columns

    float4 acc = make_float4(0.f, 0.f, 0.f, 0.f);

    int e = start;
    // unroll by 2 for memory-level parallelism
    for (; e + 1 < end; e += 2) {
        int c0 = __ldg(g_cols + e);
        int c1 = __ldg(g_cols + e + 1);
        float w0 = __ldg(g_wts + e);
        float w1 = __ldg(g_wts + e + 1);
        float4 v0 = __ldg((const float4*)(g_support + (size_t)c0 * D) + t);
        float4 v1 = __ldg((const float4*)(g_support + (size_t)c1 * D) + t);
        acc.x += w0 * v0.x + w1 * v1.x;
        acc.y += w0 * v0.y + w1 * v1.y;
        acc.z += w0 * v0.z + w1 * v1.z;
        acc.w += w0 * v0.w + w1 * v1.w;
    }
    if (e < end) {
        int c0 = __ldg(g_cols + e);
        float w0 = __ldg(g_wts + e);
        float4 v0 = __ldg((const float4*)(g_support + (size_t)c0 * D) + t);
        acc.x += w0 * v0.x;
        acc.y += w0 * v0.y;
        acc.z += w0 * v0.z;
        acc.w += w0 * v0.w;
    }

    float4 b = __ldg((const float4*)bias + t);
    acc.x += b.x; acc.y += b.y; acc.z += b.z; acc.w += b.w;
    *((float4*)(out + (size_t)r * D) + t) = acc;
}

// ---------------- launch ----------------
extern "C" void kernel_launch(void* const* d_in, const int* in_sizes, int n_in,
                              void* d_out, int out_size) {
    const float* x    = (const float*)d_in[0];
    const float* w    = (const float*)d_in[1];
    const float* bias = (const float*)d_in[2];
    const int*   row  = (const int*)d_in[3];
    const int*   col  = (const int*)d_in[4];
    const float* ew   = (const float*)d_in[5];
    float* out = (float*)d_out;

    // stage 1: dense GEMM -> g_support
    dim3 gemm_grid(D / BN, (N_NODES + BM - 1) / BM);
    sgemm_kernel<<<gemm_grid, 256>>>(x, w, N_NODES);

    // stage 2: CSR build (independent of GEMM, same stream)
    zero_counts_kernel<<<(N_NODES + 1023) / 1024, 1024>>>();
    hist_kernel<<<(N_EDGES + 255) / 256, 256>>>(row);
    scan1_kernel<<<SCAN_NBLK, SCAN_B>>>();
    scan2_kernel<<<1, 32>>>();
    scan3_kernel<<<SCAN_NBLK, SCAN_B>>>();
    scatter_kernel<<<(N_EDGES + 255) / 256, 256>>>(row, col, ew);

    // stage 3: gather-accumulate SpMM + bias
    spmm_kernel<<<N_NODES, 128>>>(bias, out);
}

// round 9
// speedup vs baseline: 1.4276x; 1.4276x over previous
#include <cuda_runtime.h>
#include <cuda_bf16.h>
#include <cstdint>

#define N_NODES 50000
#define N_EDGES 1600000
#define D 512

// ---------------- scratch (static device globals; no runtime alloc) ----------------
__device__ float g_support[(size_t)N_NODES * D];            // X @ W  (102.4 MB)
__device__ __nv_bfloat16 g_xhi[(size_t)N_NODES * D];        // 51.2 MB
__device__ __nv_bfloat16 g_xlo[(size_t)N_NODES * D];        // 51.2 MB
__device__ __nv_bfloat16 g_wthi[D * D];                     // W^T hi  [n][k]
__device__ __nv_bfloat16 g_wtlo[D * D];                     // W^T lo  [n][k]
__device__ int   g_counts[N_NODES];
__device__ int   g_rowptr[N_NODES + 1];
__device__ int   g_cursor[N_NODES];
__device__ int   g_blksum[64];
__device__ int   g_cols[N_EDGES];
__device__ float g_wts[N_EDGES];

// ---------------- helpers ----------------
__device__ __forceinline__ uint32_t smem_to_u32(const void* p) {
    uint32_t a;
    asm("{ .reg .u64 t; cvta.to.shared.u64 t, %1; cvt.u32.u64 %0, t; }" : "=r"(a) : "l"(p));
    return a;
}

__device__ __forceinline__ void ldsm_x4(uint32_t* r, uint32_t addr) {
    asm volatile("ldmatrix.sync.aligned.m8n8.x4.shared.b16 {%0,%1,%2,%3}, [%4];"
                 : "=r"(r[0]), "=r"(r[1]), "=r"(r[2]), "=r"(r[3]) : "r"(addr));
}
__device__ __forceinline__ void ldsm_x2(uint32_t* r, uint32_t addr) {
    asm volatile("ldmatrix.sync.aligned.m8n8.x2.shared.b16 {%0,%1}, [%2];"
                 : "=r"(r[0]), "=r"(r[1]) : "r"(addr));
}
__device__ __forceinline__ void mma_bf16(float* c, const uint32_t* a, const uint32_t* b) {
    asm volatile(
        "mma.sync.aligned.m16n8k16.row.col.f32.bf16.bf16.f32 "
        "{%0,%1,%2,%3}, {%4,%5,%6,%7}, {%8,%9}, {%0,%1,%2,%3};"
        : "+f"(c[0]), "+f"(c[1]), "+f"(c[2]), "+f"(c[3])
        : "r"(a[0]), "r"(a[1]), "r"(a[2]), "r"(a[3]), "r"(b[0]), "r"(b[1]));
}

// ---------------- conversion: fp32 -> bf16 hi/lo split ----------------
__global__ __launch_bounds__(256) void split_x_kernel(const float* __restrict__ x) {
    size_t i = ((size_t)blockIdx.x * blockDim.x + threadIdx.x) * 4;
    if (i >= (size_t)N_NODES * D) return;
    float4 v = *(const float4*)(x + i);
    __nv_bfloat16 h0 = __float2bfloat16(v.x);
    __nv_bfloat16 h1 = __float2bfloat16(v.y);
    __nv_bfloat16 h2 = __float2bfloat16(v.z);
    __nv_bfloat16 h3 = __float2bfloat16(v.w);
    __nv_bfloat16 l0 = __float2bfloat16(v.x - __bfloat162float(h0));
    __nv_bfloat16 l1 = __float2bfloat16(v.y - __bfloat162float(h1));
    __nv_bfloat16 l2 = __float2bfloat16(v.z - __bfloat162float(h2));
    __nv_bfloat16 l3 = __float2bfloat16(v.w - __bfloat162float(h3));
    *(__nv_bfloat162*)(g_xhi + i)     = __nv_bfloat162(h0, h1);
    *(__nv_bfloat162*)(g_xhi + i + 2) = __nv_bfloat162(h2, h3);
    *(__nv_bfloat162*)(g_xlo + i)     = __nv_bfloat162(l0, l1);
    *(__nv_bfloat162*)(g_xlo + i + 2) = __nv_bfloat162(l2, l3);
}

__global__ __launch_bounds__(128) void split_w_kernel(const float* __restrict__ w) {
    int n = blockIdx.x;
    for (int k = threadIdx.x; k < D; k += blockDim.x) {
        float v = w[(size_t)k * D + n];   // transpose: wt[n][k] = w[k][n]
        __nv_bfloat16 hi = __float2bfloat16(v);
        __nv_bfloat16 lo = __float2bfloat16(v - __bfloat162float(hi));
        g_wthi[(size_t)n * D + k] = hi;
        g_wtlo[(size_t)n * D + k] = lo;
    }
}

// ---------------- HMMA GEMM: support = X @ W (split-bf16, 3 passes) ----------------
// CTA tile 128x128, K-chunk 32. 8 warps: warp tile 32(M) x 64(N).
// B operand = W^T stored [n][k] row-major == col-major KxN, as mma.row.col wants.
#define BM 128
#define BN 128
#define BK 32
#define LDA 40              // padded row length in bf16 (80 bytes; conflict-free ldmatrix)
#define NKCH (D / BK)       // 16

__global__ __launch_bounds__(256, 1) void gemm_mma_kernel() {
    __shared__ __nv_bfloat16 sAhi[BM * LDA];
    __shared__ __nv_bfloat16 sAlo[BM * LDA];
    __shared__ __nv_bfloat16 sBhi[BN * LDA];
    __shared__ __nv_bfloat16 sBlo[BN * LDA];

    const int tid = threadIdx.x;
    const int lane = tid & 31;
    const int wid = tid >> 5;
    const int wm = wid & 3;          // 4 warps along M, 32 rows each
    const int wn = wid >> 2;         // 2 warps along N, 64 cols each
    const int m0 = blockIdx.y * BM;
    const int n0 = blockIdx.x * BN;

    const uint32_t sAhi_b = smem_to_u32(sAhi);
    const uint32_t sAlo_b = smem_to_u32(sAlo);
    const uint32_t sBhi_b = smem_to_u32(sBhi);
    const uint32_t sBlo_b = smem_to_u32(sBlo);

    float acc[2][8][4];
#pragma unroll
    for (int i = 0; i < 2; i++)
#pragma unroll
        for (int j = 0; j < 8; j++)
#pragma unroll
            for (int k = 0; k < 4; k++) acc[i][j][k] = 0.f;

    // loader mapping: each thread owns one (row, half-chunk): 16 bf16 = 32 bytes
    const int lrow = tid >> 1;       // 0..127
    const int lhalf = tid & 1;       // k-offset 0 or 16 bf16

    const uint4 zero4 = make_uint4(0, 0, 0, 0);

    for (int kc = 0; kc < NKCH; kc++) {
        // A tile: rows m0+lrow, cols kc*32 + lhalf*16 .. +15
        {
            int gm = m0 + lrow;
            size_t gidx = (size_t)gm * (D / 8) + kc * 4 + lhalf * 2;   // uint4 units
            uint4 vh0 = zero4, vh1 = zero4, vl0 = zero4, vl1 = zero4;
            if (gm < N_NODES) {
                const uint4* xh = (const uint4*)g_xhi;
                const uint4* xl = (const uint4*)g_xlo;
                vh0 = xh[gidx]; vh1 = xh[gidx + 1];
                vl0 = xl[gidx]; vl1 = xl[gidx + 1];
            }
            char* dsth = (char*)sAhi + lrow * 80 + lhalf * 32;
            char* dstl = (char*)sAlo + lrow * 80 + lhalf * 32;
            *(uint4*)dsth = vh0; *(uint4*)(dsth + 16) = vh1;
            *(uint4*)dstl = vl0; *(uint4*)(dstl + 16) = vl1;
        }
        // B tile: W^T rows n0+lrow, cols kc*32 + lhalf*16 (always in range: D=512)
        {
            int gn = n0 + lrow;
            size_t gidx = (size_t)gn * (D / 8) + kc * 4 + lhalf * 2;
            const uint4* bh = (const uint4*)g_wthi;
            const uint4* bl = (const uint4*)g_wtlo;
            char* dsth = (char*)sBhi + lrow * 80 + lhalf * 32;
            char* dstl = (char*)sBlo + lrow * 80 + lhalf * 32;
            *(uint4*)dsth = bh[gidx]; *(uint4*)(dsth + 16) = bh[gidx + 1];
            *(uint4*)dstl = bl[gidx]; *(uint4*)(dstl + 16) = bl[gidx + 1];
        }
        __syncthreads();

#pragma unroll
        for (int ks = 0; ks < 2; ks++) {          // two k16 steps inside the 32-chunk
            uint32_t a_hi[2][4], a_lo[2][4];
#pragma unroll
            for (int mf = 0; mf < 2; mf++) {
                uint32_t r = wm * 32 + mf * 16 + (lane & 15);
                uint32_t off = r * 80 + ks * 32 + (lane >> 4) * 16;
                ldsm_x4(a_hi[mf], sAhi_b + off);
                ldsm_x4(a_lo[mf], sAlo_b + off);
            }
#pragma unroll
            for (int nf = 0; nf < 8; nf++) {
                int l = lane & 15;
                uint32_t rb = wn * 64 + nf * 8 + (l & 7);
                uint32_t boff = rb * 80 + ks * 32 + (l >> 3) * 16;
                uint32_t b_hi[2], b_lo[2];
                ldsm_x2(b_hi, sBhi_b + boff);
                ldsm_x2(b_lo, sBlo_b + boff);
#pragma unroll
                for (int mf = 0; mf < 2; mf++) {
                    mma_bf16(acc[mf][nf], a_hi[mf], b_hi);   // hi*hi
                    mma_bf16(acc[mf][nf], a_hi[mf], b_lo);   // hi*lo
                    mma_bf16(acc[mf][nf], a_lo[mf], b_hi);   // lo*hi
                }
            }
        }
        __syncthreads();
    }

    // epilogue: acc -> g_support
    const int gm_base = m0 + wm * 32;
    const int gn_base = n0 + wn * 64;
#pragma unroll
    for (int mf = 0; mf < 2; mf++) {
        int r0 = gm_base + mf * 16 + (lane >> 2);
        int r1 = r0 + 8;
#pragma unroll
        for (int nf = 0; nf < 8; nf++) {
            int cc = gn_base + nf * 8 + (lane & 3) * 2;
            if (r0 < N_NODES)
                *(float2*)(g_support + (size_t)r0 * D + cc) = make_float2(acc[mf][nf][0], acc[mf][nf][1]);
            if (r1 < N_NODES)
                *(float2*)(g_support + (size_t)r1 * D + cc) = make_float2(acc[mf][nf][2], acc[mf][nf][3]);
        }
    }
}

// ---------------- CSR build ----------------
__global__ void zero_counts_kernel() {
    int i = blockIdx.x * blockDim.x + threadIdx.x;
    if (i < N_NODES) g_counts[i] = 0;
}

__global__ void hist_kernel(const int* __restrict__ row) {
    int e = blockIdx.x * blockDim.x + threadIdx.x;
    if (e < N_EDGES) atomicAdd(&g_counts[row[e]], 1);
}

#define SCAN_B 1024
#define SCAN_NBLK ((N_NODES + SCAN_B - 1) / SCAN_B)   // 49

__global__ __launch_bounds__(SCAN_B) void scan1_kernel() {
    __shared__ int sh[SCAN_B];
    int i = blockIdx.x * SCAN_B + threadIdx.x;
    int v = (i < N_NODES) ? g_counts[i] : 0;
    sh[threadIdx.x] = v;
    __syncthreads();
    for (int off = 1; off < SCAN_B; off <<= 1) {
        int t = (threadIdx.x >= off) ? sh[threadIdx.x - off] : 0;
        __syncthreads();
        sh[threadIdx.x] += t;
        __syncthreads();
    }
    if (i < N_NODES) g_rowptr[i] = sh[threadIdx.x] - v;
    if (threadIdx.x == SCAN_B - 1) g_blksum[blockIdx.x] = sh[SCAN_B - 1];
}

__global__ void scan2_kernel() {
    if (threadIdx.x == 0) {
        int acc = 0;
        for (int b = 0; b < SCAN_NBLK; b++) {
            int t = g_blksum[b];
            g_blksum[b] = acc;
            acc += t;
        }
    }
}

__global__ __launch_bounds__(SCAN_B) void scan3_kernel() {
    int i = blockIdx.x * SCAN_B + threadIdx.x;
    if (i < N_NODES) {
        int v = g_rowptr[i] + g_blksum[blockIdx.x];
        g_rowptr[i] = v;
        g_cursor[i] = v;
    }
    if (i == 0) g_rowptr[N_NODES] = N_EDGES;
}

__global__ void scatter_kernel(const int* __restrict__ row, const int* __restrict__ col,
                               const float* __restrict__ ew) {
    int e = blockIdx.x * blockDim.x + threadIdx.x;
    if (e < N_EDGES) {
        int r = row[e];
        int p = atomicAdd(&g_cursor[r], 1);
        g_cols[p] = col[e];
        g_wts[p] = ew[e];
    }
}

// ---------------- SpMM over half the columns (L2-resident phase) ----------------
__global__ __launch_bounds__(64) void spmm_half_kernel(const float* __restrict__ bias,
                                                       float* __restrict__ out, int half) {
    int r = blockIdx.x;
    int start = g_rowptr[r];
    int end = g_rowptr[r + 1];
    int cb = half * 64 + threadIdx.x;     // float4 index within 128-float4 row

    const float4* sup = (const float4*)g_support;
    float4 acc = make_float4(0.f, 0.f, 0.f, 0.f);

    int e = start;
    for (; e + 3 < end; e += 4) {
        int c0 = __ldg(g_cols + e);
        int c1 = __ldg(g_cols + e + 1);
        int c2 = __ldg(g_cols + e + 2);
        int c3 = __ldg(g_cols + e + 3);
        float w0 = __ldg(g_wts + e);
        float w1 = __ldg(g_wts + e + 1);
        float w2 = __ldg(g_wts + e + 2);
        float w3 = __ldg(g_wts + e + 3);
        float4 v0 = __ldg(sup + (size_t)c0 * 128 + cb);
        float4 v1 = __ldg(sup + (size_t)c1 * 128 + cb);
        float4 v2 = __ldg(sup + (size_t)c2 * 128 + cb);
        float4 v3 = __ldg(sup + (size_t)c3 * 128 + cb);
        acc.x += w0 * v0.x + w1 * v1.x + w2 * v2.x + w3 * v3.x;
        acc.y += w0 * v0.y + w1 * v1.y + w2 * v2.y + w3 * v3.y;
        acc.z += w0 * v0.z + w1 * v1.z + w2 * v2.z + w3 * v3.z;
        acc.w += w0 * v0.w + w1 * v1.w + w2 * v2.w + w3 * v3.w;
    }
    for (; e < end; e++) {
        int c0 = __ldg(g_cols + e);
        float w0 = __ldg(g_wts + e);
        float4 v0 = __ldg(sup + (size_t)c0 * 128 + cb);
        acc.x += w0 * v0.x;
        acc.y += w0 * v0.y;
        acc.z += w0 * v0.z;
        acc.w += w0 * v0.w;
    }

    float4 b = __ldg((const float4*)bias + cb);
    acc.x += b.x; acc.y += b.y; acc.z += b.z; acc.w += b.w;
    __stcs((float4*)(out + (size_t)r * D) + cb, acc);
}

// ---------------- launch ----------------
extern "C" void kernel_launch(void* const* d_in, const int* in_sizes, int n_in,
                              void* d_out, int out_size) {
    const float* x    = (const float*)d_in[0];
    const float* w    = (const float*)d_in[1];
    const float* bias = (const float*)d_in[2];
    const int*   row  = (const int*)d_in[3];
    const int*   col  = (const int*)d_in[4];
    const float* ew   = (const float*)d_in[5];
    float* out = (float*)d_out;

    // stage 1: split fp32 -> bf16 hi/lo, then HMMA GEMM
    size_t xe = (size_t)N_NODES * D;
    split_x_kernel<<<(unsigned)((xe / 4 + 255) / 256), 256>>>(x);
    split_w_kernel<<<D, 128>>>(w);
    dim3 gemm_grid(D / BN, (N_NODES + BM - 1) / BM);
    gemm_mma_kernel<<<gemm_grid, 256>>>();

    // stage 2: CSR build
    zero_counts_kernel<<<(N_NODES + 1023) / 1024, 1024>>>();
    hist_kernel<<<(N_EDGES + 255) / 256, 256>>>(row);
    scan1_kernel<<<SCAN_NBLK, SCAN_B>>>();
    scan2_kernel<<<1, 32>>>();
    scan3_kernel<<<SCAN_NBLK, SCAN_B>>>();
    scatter_kernel<<<(N_EDGES + 255) / 256, 256>>>(row, col, ew);

    // stage 3: gather-accumulate SpMM + bias, two L2-resident column phases
    spmm_half_kernel<<<N_NODES, 64>>>(bias, out, 0);
    spmm_half_kernel<<<N_NODES, 64>>>(bias, out, 1);
}